// round 4
// baseline (speedup 1.0000x reference)
#include <cuda_runtime.h>
#include <cstdint>
#include <cstddef>

// Problem constants
#define cN0 1000000
#define cN1 200000
#define cN2 20000
#define cN3 2048
#define cE0 2000000
#define cE1 200000
#define cE2 20480
#define cIN 128
#define cHID 256
#define cOUT 47

// ---------------- device scratch (allocation-free rule: __device__ globals) ----------------
__device__ float g_agg0[(size_t)cN1 * cIN];    // 102.4 MB
__device__ float g_deg0[cN1];
__device__ float g_h1[(size_t)cN1 * cHID];     // 204.8 MB
__device__ float g_agg1[(size_t)cN2 * cHID];   // 20.5 MB
__device__ float g_deg1[cN2];
__device__ float g_h2[(size_t)cN2 * cHID];     // 20.5 MB
__device__ float g_agg2[(size_t)cN3 * cHID];   // 2.1 MB
__device__ float g_deg2[cN3];

// ---------------- zero kernel ----------------
__global__ void zero_kernel(float4* __restrict__ p, int n4) {
    int i = blockIdx.x * blockDim.x + threadIdx.x;
    if (i < n4) p[i] = make_float4(0.f, 0.f, 0.f, 0.f);
}

// ---------------- edge scatter: warp per edge, vectorized fp32 reduction ----------------
template <int F>
__global__ void scatter_kernel(const float* __restrict__ H,
                               const int* __restrict__ src,
                               const int* __restrict__ dst,
                               float* __restrict__ agg,
                               float* __restrict__ deg,
                               int E) {
    int warp = (blockIdx.x * blockDim.x + threadIdx.x) >> 5;
    int lane = threadIdx.x & 31;
    if (warp >= E) return;
    int s = src[warp];
    int d = dst[warp];
    const float4* hs = (const float4*)(H + (size_t)s * F);
    float* ad = agg + (size_t)d * F;
#pragma unroll
    for (int i = 0; i < F / 128; i++) {
        float4 v = hs[lane + i * 32];
        float* p = ad + (size_t)(lane + i * 32) * 4;
        asm volatile("red.global.add.v4.f32 [%0], {%1,%2,%3,%4};"
                     :: "l"(p), "f"(v.x), "f"(v.y), "f"(v.z), "f"(v.w)
                     : "memory");
    }
    if (lane == 0) atomicAdd(deg + d, 1.0f);
}

// ---------------- tf32 helpers ----------------
__device__ __forceinline__ uint32_t f2tf32(float f) {
    uint32_t u;
    asm("cvt.rna.tf32.f32 %0, %1;" : "=r"(u) : "f"(f));
    return u;
}

// ---------------- fused SAGE GEMM: C = relu?([Aself | Aneigh/deg] @ [Bself; Bneigh] + bias) ----
// C is [M][256] row-major, B's are [K][256] row-major.
// Block tile 128x128, BK=32, 256 threads, tf32 mma.sync m16n8k8 fp32 accumulate.
template <bool RELU>
__global__ void __launch_bounds__(256, 2) gemm_sage(
    int M, int K1, int K2,
    const float* __restrict__ Aself, int ldAs,
    const float* __restrict__ Aneigh, int ldAn,
    const float* __restrict__ deg,
    const float* __restrict__ Bself,
    const float* __restrict__ Bneigh,
    const float* __restrict__ bias,
    float* __restrict__ C) {
    constexpr int BM = 128, BN = 128, BK = 32, SST = 36;  // smem row stride (pad 4)
    __shared__ __align__(16) float As[BM * SST];          // [row][k]
    __shared__ __align__(16) float Bs[BN * SST];          // [n][k] (transposed)

    const int tid = threadIdx.x;
    const int lane = tid & 31;
    const int warp = tid >> 5;
    const int wm = (warp & 3) * 32;   // warp m offset in tile
    const int wn = (warp >> 2) * 64;  // warp n offset in tile
    const int m0 = blockIdx.y * BM;
    const int n0 = blockIdx.x * BN;
    const int Ktot = K1 + K2;

    float c[2][8][4] = {};

    for (int kt = 0; kt < Ktot; kt += BK) {
        // ---- load A tile (with on-the-fly degree normalization of neigh half) ----
#pragma unroll
        for (int i = 0; i < 4; i++) {
            int row = (tid >> 3) + i * 32;
            int col = (tid & 7) * 4;
            int kg = kt + col;
            int gm = m0 + row;
            float4 v = make_float4(0.f, 0.f, 0.f, 0.f);
            if (gm < M) {
                if (kg < K1) {
                    v = *(const float4*)(Aself + (size_t)gm * ldAs + kg);
                } else {
                    v = *(const float4*)(Aneigh + (size_t)gm * ldAn + (kg - K1));
                    float inv = 1.0f / fmaxf(deg[gm], 1.0f);
                    v.x *= inv; v.y *= inv; v.z *= inv; v.w *= inv;
                }
            }
            uint32_t* s = (uint32_t*)&As[row * SST + col];
            s[0] = f2tf32(v.x); s[1] = f2tf32(v.y);
            s[2] = f2tf32(v.z); s[3] = f2tf32(v.w);
        }
        // ---- load B tile, store transposed [n][k] ----
        uint32_t* bs = (uint32_t*)Bs;
#pragma unroll
        for (int i = 0; i < 4; i++) {
            int j = tid + i * 256;       // float4 index within 32x128 tile
            int krow = j >> 5;           // 0..31
            int coln = (j & 31) * 4;     // n within tile
            int kg = kt + krow;
            const float* Bp = (kg < K1) ? (Bself + (size_t)kg * 256)
                                        : (Bneigh + (size_t)(kg - K1) * 256);
            float4 v = *(const float4*)(Bp + n0 + coln);
            bs[(coln + 0) * SST + krow] = f2tf32(v.x);
            bs[(coln + 1) * SST + krow] = f2tf32(v.y);
            bs[(coln + 2) * SST + krow] = f2tf32(v.z);
            bs[(coln + 3) * SST + krow] = f2tf32(v.w);
        }
        __syncthreads();

        const uint32_t* Ap = (const uint32_t*)As;
        const uint32_t* Bp = (const uint32_t*)Bs;
#pragma unroll
        for (int ks = 0; ks < 4; ks++) {
            const int k0 = ks * 8;
            uint32_t a[2][4], b[8][2];
#pragma unroll
            for (int mf = 0; mf < 2; mf++) {
                int r = wm + mf * 16 + (lane >> 2);
                int kk = k0 + (lane & 3);
                a[mf][0] = Ap[r * SST + kk];
                a[mf][1] = Ap[(r + 8) * SST + kk];
                a[mf][2] = Ap[r * SST + kk + 4];
                a[mf][3] = Ap[(r + 8) * SST + kk + 4];
            }
#pragma unroll
            for (int nf = 0; nf < 8; nf++) {
                int cn = wn + nf * 8 + (lane >> 2);
                int kk = k0 + (lane & 3);
                b[nf][0] = Bp[cn * SST + kk];
                b[nf][1] = Bp[cn * SST + kk + 4];
            }
#pragma unroll
            for (int mf = 0; mf < 2; mf++)
#pragma unroll
                for (int nf = 0; nf < 8; nf++)
                    asm volatile(
                        "mma.sync.aligned.m16n8k8.row.col.f32.tf32.tf32.f32 "
                        "{%0,%1,%2,%3},{%4,%5,%6,%7},{%8,%9},{%0,%1,%2,%3};"
                        : "+f"(c[mf][nf][0]), "+f"(c[mf][nf][1]),
                          "+f"(c[mf][nf][2]), "+f"(c[mf][nf][3])
                        : "r"(a[mf][0]), "r"(a[mf][1]), "r"(a[mf][2]), "r"(a[mf][3]),
                          "r"(b[nf][0]), "r"(b[nf][1]));
        }
        __syncthreads();
    }

    // ---- epilogue: bias (+ relu) + store ----
#pragma unroll
    for (int mf = 0; mf < 2; mf++) {
#pragma unroll
        for (int nf = 0; nf < 8; nf++) {
            int col = n0 + wn + nf * 8 + (lane & 3) * 2;
            float bb0 = bias[col];
            float bb1 = bias[col + 1];
#pragma unroll
            for (int h = 0; h < 2; h++) {
                int row = m0 + wm + mf * 16 + (lane >> 2) + h * 8;
                if (row < M) {
                    float v0 = c[mf][nf][h * 2 + 0] + bb0;
                    float v1 = c[mf][nf][h * 2 + 1] + bb1;
                    if (RELU) { v0 = fmaxf(v0, 0.f); v1 = fmaxf(v1, 0.f); }
                    *(float2*)(C + (size_t)row * 256 + col) = make_float2(v0, v1);
                }
            }
        }
    }
}

// ---------------- output layer: [2048 x 512] @ [512 x 47] + b, no relu ----------------
__global__ void out_layer_kernel(const float* __restrict__ h2,
                                 const float* __restrict__ agg2,
                                 const float* __restrict__ deg2,
                                 const float* __restrict__ Ws,
                                 const float* __restrict__ Wn,
                                 const float* __restrict__ bias,
                                 float* __restrict__ out) {
    __shared__ float s[512];
    int r = blockIdx.x;
    int tid = threadIdx.x;  // 64 threads
    float inv = 1.0f / fmaxf(deg2[r], 1.0f);
    for (int k = tid; k < 256; k += 64) {
        s[k] = h2[(size_t)r * 256 + k];
        s[256 + k] = agg2[(size_t)r * 256 + k] * inv;
    }
    __syncthreads();
    if (tid < cOUT) {
        float acc = bias[tid];
#pragma unroll 4
        for (int k = 0; k < 256; k++) {
            acc += s[k] * Ws[k * cOUT + tid];
            acc += s[256 + k] * Wn[k * cOUT + tid];
        }
        out[r * cOUT + tid] = acc;
    }
}

// ---------------- launch ----------------
static inline void launch_zero(float* p, size_t n) {
    int n4 = (int)(n / 4);
    zero_kernel<<<(n4 + 255) / 256, 256>>>((float4*)p, n4);
}

extern "C" void kernel_launch(void* const* d_in, const int* in_sizes, int n_in,
                              void* d_out, int out_size) {
    const float* x   = (const float*)d_in[0];
    const int* src0  = (const int*)d_in[1];
    const int* dst0  = (const int*)d_in[2];
    const int* src1  = (const int*)d_in[3];
    const int* dst1  = (const int*)d_in[4];
    const int* src2  = (const int*)d_in[5];
    const int* dst2  = (const int*)d_in[6];
    const float* Ws0 = (const float*)d_in[7];
    const float* Wn0 = (const float*)d_in[8];
    const float* b0  = (const float*)d_in[9];
    const float* Ws1 = (const float*)d_in[10];
    const float* Wn1 = (const float*)d_in[11];
    const float* b1  = (const float*)d_in[12];
    const float* Ws2 = (const float*)d_in[13];
    const float* Wn2 = (const float*)d_in[14];
    const float* b2  = (const float*)d_in[15];
    float* out = (float*)d_out;

    float *agg0, *deg0, *h1, *agg1, *deg1, *h2, *agg2, *deg2;
    cudaGetSymbolAddress((void**)&agg0, g_agg0);
    cudaGetSymbolAddress((void**)&deg0, g_deg0);
    cudaGetSymbolAddress((void**)&h1,   g_h1);
    cudaGetSymbolAddress((void**)&agg1, g_agg1);
    cudaGetSymbolAddress((void**)&deg1, g_deg1);
    cudaGetSymbolAddress((void**)&h2,   g_h2);
    cudaGetSymbolAddress((void**)&agg2, g_agg2);
    cudaGetSymbolAddress((void**)&deg2, g_deg2);

    // zero accumulators
    launch_zero(agg0, (size_t)cN1 * cIN);
    launch_zero(deg0, cN1);
    launch_zero(agg1, (size_t)cN2 * cHID);
    launch_zero(deg1, cN2);
    launch_zero(agg2, (size_t)cN3 * cHID);
    launch_zero(deg2, cN3);

    // ---- layer 0 ----
    {
        int blocks = (cE0 + 7) / 8;  // 8 warps per 256-thread block, warp per edge
        scatter_kernel<cIN><<<blocks, 256>>>(x, src0, dst0, agg0, deg0, cE0);
        dim3 grid(256 / 128, (cN1 + 127) / 128);
        gemm_sage<true><<<grid, 256>>>(cN1, cIN, cIN, x, cIN, agg0, cIN, deg0,
                                       Ws0, Wn0, b0, h1);
    }
    // ---- layer 1 ----
    {
        int blocks = (cE1 + 7) / 8;
        scatter_kernel<cHID><<<blocks, 256>>>(h1, src1, dst1, agg1, deg1, cE1);
        dim3 grid(256 / 128, (cN2 + 127) / 128);
        gemm_sage<true><<<grid, 256>>>(cN2, cHID, cHID, h1, cHID, agg1, cHID, deg1,
                                       Ws1, Wn1, b1, h2);
    }
    // ---- layer 2 (output) ----
    {
        int blocks = (cE2 + 7) / 8;
        scatter_kernel<cHID><<<blocks, 256>>>(h2, src2, dst2, agg2, deg2, cE2);
        out_layer_kernel<<<cN3, 64>>>(h2, agg2, deg2, Ws2, Wn2, b2, out);
    }
    (void)in_sizes; (void)n_in; (void)out_size;
}

// round 5
// speedup vs baseline: 1.7740x; 1.7740x over previous
#include <cuda_runtime.h>
#include <cstdint>
#include <cstddef>

// Problem constants
#define cN0 1000000
#define cN1 200000
#define cN2 20000
#define cN3 2048
#define cE0 2000000
#define cE1 200000
#define cE2 20480
#define cIN 128
#define cHID 256
#define cOUT 47

// ---------------- device scratch (allocation-free rule: __device__ globals) ----------------
__device__ float g_hn0[(size_t)cN1 * cIN];    // normalized neighbor agg, layer 0 (102 MB)
__device__ float g_h1 [(size_t)cN1 * cHID];   // layer-0 output (205 MB)
__device__ float g_hn1[(size_t)cN2 * cHID];   // 20.5 MB
__device__ float g_h2 [(size_t)cN2 * cHID];   // 20.5 MB
__device__ float g_hn2[(size_t)cN3 * cHID];   // 2.1 MB
__device__ int   g_counts[cN1];
__device__ int   g_offs[cN1];
__device__ int   g_cursor[cN1];
__device__ int   g_esrc[cE0];                 // permuted src indices (CSR payload)
__device__ int   g_bsums[256];

// ---------------- small utility kernels ----------------
__global__ void zero_int(int* __restrict__ p, int n) {
    int i = blockIdx.x * blockDim.x + threadIdx.x;
    if (i < n) p[i] = 0;
}

__global__ void hist_kernel(const int* __restrict__ dst, int E, int* __restrict__ counts) {
    int i = blockIdx.x * blockDim.x + threadIdx.x;
    if (i < E) atomicAdd(&counts[dst[i]], 1);
}

// ---- hierarchical exclusive scan over n<=256*1024 elements ----
__global__ void scan1(const int* __restrict__ counts, int n,
                      int* __restrict__ offs, int* __restrict__ bsums) {
    __shared__ int sh[256];
    int t = threadIdx.x;
    int base = blockIdx.x * 1024 + t * 4;
    int v0 = 0, v1 = 0, v2 = 0, v3 = 0;
    if (base + 3 < n) {
        int4 v = *(const int4*)(counts + base);
        v0 = v.x; v1 = v.y; v2 = v.z; v3 = v.w;
    } else {
        if (base     < n) v0 = counts[base];
        if (base + 1 < n) v1 = counts[base + 1];
        if (base + 2 < n) v2 = counts[base + 2];
        if (base + 3 < n) v3 = counts[base + 3];
    }
    int s = v0 + v1 + v2 + v3;
    sh[t] = s; __syncthreads();
    for (int off = 1; off < 256; off <<= 1) {
        int tmp = (t >= off) ? sh[t - off] : 0;
        __syncthreads();
        sh[t] += tmp;
        __syncthreads();
    }
    int ex = sh[t] - s;
    if (base     < n) offs[base]     = ex;
    if (base + 1 < n) offs[base + 1] = ex + v0;
    if (base + 2 < n) offs[base + 2] = ex + v0 + v1;
    if (base + 3 < n) offs[base + 3] = ex + v0 + v1 + v2;
    if (t == 255) bsums[blockIdx.x] = sh[255];
}

__global__ void scan2(int* __restrict__ bsums, int nB) {
    __shared__ int sh[256];
    int t = threadIdx.x;
    int v = (t < nB) ? bsums[t] : 0;
    sh[t] = v; __syncthreads();
    for (int off = 1; off < 256; off <<= 1) {
        int tmp = (t >= off) ? sh[t - off] : 0;
        __syncthreads();
        sh[t] += tmp;
        __syncthreads();
    }
    if (t < nB) bsums[t] = sh[t] - v;
}

__global__ void scan3(int* __restrict__ offs, const int* __restrict__ bsums, int n,
                      int* __restrict__ cursor) {
    int t = threadIdx.x;
    int base = blockIdx.x * 1024 + t * 4;
    int add = bsums[blockIdx.x];
#pragma unroll
    for (int j = 0; j < 4; j++) {
        int i = base + j;
        if (i < n) {
            int v = offs[i] + add;
            offs[i] = v;
            cursor[i] = v;
        }
    }
}

__global__ void scatter_edges(const int* __restrict__ src, const int* __restrict__ dst,
                              int E, int* __restrict__ cursor, int* __restrict__ esrc) {
    int e = blockIdx.x * blockDim.x + threadIdx.x;
    if (e < E) {
        int slot = atomicAdd(&cursor[dst[e]], 1);
        esrc[slot] = src[e];
    }
}

// ---------------- aggregation: warp per dst, write-once, pre-normalized ----------------
template <int F>
__global__ void aggregate_kernel(const float* __restrict__ H,
                                 const int* __restrict__ offs,
                                 const int* __restrict__ esrc,
                                 int n, int E,
                                 float* __restrict__ outAgg) {
    int d = (blockIdx.x * blockDim.x + threadIdx.x) >> 5;
    int lane = threadIdx.x & 31;
    if (d >= n) return;
    int start = offs[d];
    int end = (d + 1 < n) ? offs[d + 1] : E;
    float4 acc[F / 128];
#pragma unroll
    for (int j = 0; j < F / 128; j++) acc[j] = make_float4(0.f, 0.f, 0.f, 0.f);
    for (int i = start; i < end; i++) {
        int s = esrc[i];
        const float4* hs = (const float4*)(H + (size_t)s * F);
#pragma unroll
        for (int j = 0; j < F / 128; j++) {
            float4 v = hs[lane + 32 * j];
            acc[j].x += v.x; acc[j].y += v.y; acc[j].z += v.z; acc[j].w += v.w;
        }
    }
    float inv = 1.0f / fmaxf((float)(end - start), 1.0f);
    float4* op = (float4*)(outAgg + (size_t)d * F);
#pragma unroll
    for (int j = 0; j < F / 128; j++) {
        acc[j].x *= inv; acc[j].y *= inv; acc[j].z *= inv; acc[j].w *= inv;
        op[lane + 32 * j] = acc[j];
    }
}

// ---------------- tf32 helper ----------------
__device__ __forceinline__ uint32_t f2tf32(float f) {
    uint32_t u;
    asm("cvt.rna.tf32.f32 %0, %1;" : "=r"(u) : "f"(f));
    return u;
}

// ---------------- fused SAGE GEMM ----------------
// C = relu([Aself | Aneigh] @ [Bself; Bneigh] + bias), Aneigh pre-normalized.
// BM=128, BN=256, BK=32, 512 threads, cp.async double buffer, swizzled fp32 smem,
// tf32 mma.sync m16n8k8 fp32-accumulate.
template <bool RELU>
__global__ void __launch_bounds__(512, 1) gemm_sage(
    int M, int K1, int K2,
    const float* __restrict__ Aself, int ldAs,
    const float* __restrict__ Aneigh, int ldAn,
    const float* __restrict__ Bself,
    const float* __restrict__ Bneigh,
    const float* __restrict__ bias,
    float* __restrict__ C) {
    constexpr int BM = 128, BN = 256, BK = 32;
    extern __shared__ float sm[];
    float* As = sm;                 // [2][128][32], idx = m*32 + (k ^ (4*(m&7)))
    float* Bs = sm + 2 * BM * BK;   // [2][32][256], idx = k*256 + (n ^ (8*(k&3)))

    const int tid  = threadIdx.x;
    const int lane = tid & 31;
    const int warp = tid >> 5;
    const int wm = (warp & 3) * 32;
    const int wn = (warp >> 2) * 64;
    const int m0 = blockIdx.x * BM;
    const int T = (K1 + K2) / BK;

    float c[2][8][4] = {};

    auto issue_tile = [&](int t) {
        int kt = t * BK;
        int stage = t & 1;
        const float* Abase; int ld; int kc;
        if (kt < K1) { Abase = Aself; ld = ldAs; kc = kt; }
        else         { Abase = Aneigh; ld = ldAn; kc = kt - K1; }
#pragma unroll
        for (int it = 0; it < 2; it++) {   // A: 1024 float4 / 512 thr
            int id = tid + it * 512;
            int m  = id >> 3;
            int k4 = (id & 7) * 4;
            float* dst = As + stage * BM * BK + m * BK + (k4 ^ (4 * (m & 7)));
            const float* src = Abase + (size_t)(m0 + m) * ld + kc + k4;
            uint32_t da = (uint32_t)__cvta_generic_to_shared(dst);
            int sz = (m0 + m < M) ? 16 : 0;
            asm volatile("cp.async.cg.shared.global [%0], [%1], 16, %2;"
                         :: "r"(da), "l"(src), "r"(sz));
        }
#pragma unroll
        for (int it = 0; it < 4; it++) {   // B: 2048 float4 / 512 thr
            int id = tid + it * 512;
            int k  = id >> 6;
            int n4 = (id & 63) * 4;
            int kg = kt + k;
            const float* src = (kg < K1) ? (Bself + (size_t)kg * 256 + n4)
                                         : (Bneigh + (size_t)(kg - K1) * 256 + n4);
            float* dst = Bs + stage * BK * BN + k * BN + (n4 ^ (8 * (k & 3)));
            uint32_t da = (uint32_t)__cvta_generic_to_shared(dst);
            asm volatile("cp.async.cg.shared.global [%0], [%1], 16;"
                         :: "r"(da), "l"(src));
        }
        asm volatile("cp.async.commit_group;");
    };

    issue_tile(0);
    const int swzA = 4 * (lane >> 2);   // = 4*(r&7) for all fragment rows
    const int swzB = 8 * (lane & 3);    // = 8*(kk&3) for all fragment k's

    for (int t = 0; t < T; t++) {
        if (t + 1 < T) issue_tile(t + 1);
        else asm volatile("cp.async.commit_group;");
        asm volatile("cp.async.wait_group 1;");
        __syncthreads();
        const float* Ab = As + (t & 1) * BM * BK;
        const float* Bb = Bs + (t & 1) * BK * BN;
#pragma unroll
        for (int ks = 0; ks < 4; ks++) {
            const int k0 = ks * 8;
            const int kk = k0 + (lane & 3);
            uint32_t a[2][4], b[8][2];
#pragma unroll
            for (int mf = 0; mf < 2; mf++) {
                int r0 = wm + mf * 16 + (lane >> 2);
                a[mf][0] = f2tf32(Ab[r0 * BK + (kk ^ swzA)]);
                a[mf][1] = f2tf32(Ab[(r0 + 8) * BK + (kk ^ swzA)]);
                a[mf][2] = f2tf32(Ab[r0 * BK + ((kk + 4) ^ swzA)]);
                a[mf][3] = f2tf32(Ab[(r0 + 8) * BK + ((kk + 4) ^ swzA)]);
            }
#pragma unroll
            for (int nf = 0; nf < 8; nf++) {
                int cn = wn + nf * 8 + (lane >> 2);
                b[nf][0] = f2tf32(Bb[kk * BN + (cn ^ swzB)]);
                b[nf][1] = f2tf32(Bb[(kk + 4) * BN + (cn ^ swzB)]);
            }
#pragma unroll
            for (int mf = 0; mf < 2; mf++)
#pragma unroll
                for (int nf = 0; nf < 8; nf++)
                    asm volatile(
                        "mma.sync.aligned.m16n8k8.row.col.f32.tf32.tf32.f32 "
                        "{%0,%1,%2,%3},{%4,%5,%6,%7},{%8,%9},{%0,%1,%2,%3};"
                        : "+f"(c[mf][nf][0]), "+f"(c[mf][nf][1]),
                          "+f"(c[mf][nf][2]), "+f"(c[mf][nf][3])
                        : "r"(a[mf][0]), "r"(a[mf][1]), "r"(a[mf][2]), "r"(a[mf][3]),
                          "r"(b[nf][0]), "r"(b[nf][1]));
        }
        __syncthreads();
    }

    // epilogue: bias (+ relu) + store
#pragma unroll
    for (int mf = 0; mf < 2; mf++) {
#pragma unroll
        for (int nf = 0; nf < 8; nf++) {
            int col = wn + nf * 8 + (lane & 3) * 2;
            float bb0 = bias[col];
            float bb1 = bias[col + 1];
#pragma unroll
            for (int h = 0; h < 2; h++) {
                int row = m0 + wm + mf * 16 + (lane >> 2) + h * 8;
                if (row < M) {
                    float v0 = c[mf][nf][h * 2 + 0] + bb0;
                    float v1 = c[mf][nf][h * 2 + 1] + bb1;
                    if (RELU) { v0 = fmaxf(v0, 0.f); v1 = fmaxf(v1, 0.f); }
                    *(float2*)(C + (size_t)row * 256 + col) = make_float2(v0, v1);
                }
            }
        }
    }
}

// ---------------- output layer: [2048 x 512] @ [512 x 47] + b ----------------
__global__ void out_layer_kernel(const float* __restrict__ h2,
                                 const float* __restrict__ hn2,
                                 const float* __restrict__ Ws,
                                 const float* __restrict__ Wn,
                                 const float* __restrict__ bias,
                                 float* __restrict__ out) {
    __shared__ float s[512];
    int r = blockIdx.x;
    int tid = threadIdx.x;  // 64 threads
    for (int k = tid; k < 256; k += 64) {
        s[k]       = h2[(size_t)r * 256 + k];
        s[256 + k] = hn2[(size_t)r * 256 + k];
    }
    __syncthreads();
    if (tid < cOUT) {
        float acc = bias[tid];
#pragma unroll 4
        for (int k = 0; k < 256; k++) {
            acc += s[k] * Ws[k * cOUT + tid];
            acc += s[256 + k] * Wn[k * cOUT + tid];
        }
        out[r * cOUT + tid] = acc;
    }
}

// ---------------- host-side orchestration ----------------
static void build_and_aggregate(const float* H, const int* src, const int* dst,
                                int E, int n, int F, float* outAgg,
                                int* counts, int* offs, int* cursor, int* esrc, int* bsums) {
    zero_int<<<(n + 255) / 256, 256>>>(counts, n);
    hist_kernel<<<(E + 255) / 256, 256>>>(dst, E, counts);
    int nB = (n + 1023) / 1024;
    scan1<<<nB, 256>>>(counts, n, offs, bsums);
    scan2<<<1, 256>>>(bsums, nB);
    scan3<<<nB, 256>>>(offs, bsums, n, cursor);
    scatter_edges<<<(E + 255) / 256, 256>>>(src, dst, E, cursor, esrc);
    int blocks = (n + 7) / 8;   // 8 warps / 256-thread block, warp per dst
    if (F == 128) aggregate_kernel<128><<<blocks, 256>>>(H, offs, esrc, n, E, outAgg);
    else          aggregate_kernel<256><<<blocks, 256>>>(H, offs, esrc, n, E, outAgg);
}

extern "C" void kernel_launch(void* const* d_in, const int* in_sizes, int n_in,
                              void* d_out, int out_size) {
    const float* x   = (const float*)d_in[0];
    const int* src0  = (const int*)d_in[1];
    const int* dst0  = (const int*)d_in[2];
    const int* src1  = (const int*)d_in[3];
    const int* dst1  = (const int*)d_in[4];
    const int* src2  = (const int*)d_in[5];
    const int* dst2  = (const int*)d_in[6];
    const float* Ws0 = (const float*)d_in[7];
    const float* Wn0 = (const float*)d_in[8];
    const float* b0  = (const float*)d_in[9];
    const float* Ws1 = (const float*)d_in[10];
    const float* Wn1 = (const float*)d_in[11];
    const float* b1  = (const float*)d_in[12];
    const float* Ws2 = (const float*)d_in[13];
    const float* Wn2 = (const float*)d_in[14];
    const float* b2  = (const float*)d_in[15];
    float* out = (float*)d_out;

    float *hn0, *h1, *hn1, *h2, *hn2;
    int *counts, *offs, *cursor, *esrc, *bsums;
    cudaGetSymbolAddress((void**)&hn0, g_hn0);
    cudaGetSymbolAddress((void**)&h1,  g_h1);
    cudaGetSymbolAddress((void**)&hn1, g_hn1);
    cudaGetSymbolAddress((void**)&h2,  g_h2);
    cudaGetSymbolAddress((void**)&hn2, g_hn2);
    cudaGetSymbolAddress((void**)&counts, g_counts);
    cudaGetSymbolAddress((void**)&offs,   g_offs);
    cudaGetSymbolAddress((void**)&cursor, g_cursor);
    cudaGetSymbolAddress((void**)&esrc,   g_esrc);
    cudaGetSymbolAddress((void**)&bsums,  g_bsums);

    const size_t gemm_smem = (2 * 128 * 32 + 2 * 32 * 256) * sizeof(float);  // 96 KB
    cudaFuncSetAttribute(gemm_sage<true>, cudaFuncAttributeMaxDynamicSharedMemorySize,
                         (int)gemm_smem);

    // ---- layer 0 ----
    build_and_aggregate(x, src0, dst0, cE0, cN1, cIN, hn0, counts, offs, cursor, esrc, bsums);
    gemm_sage<true><<<(cN1 + 127) / 128, 512, gemm_smem>>>(
        cN1, cIN, cIN, x, cIN, hn0, cIN, Ws0, Wn0, b0, h1);

    // ---- layer 1 ----
    build_and_aggregate(h1, src1, dst1, cE1, cN2, cHID, hn1, counts, offs, cursor, esrc, bsums);
    gemm_sage<true><<<(cN2 + 127) / 128, 512, gemm_smem>>>(
        cN2, cHID, cHID, h1, cHID, hn1, cHID, Ws1, Wn1, b1, h2);

    // ---- layer 2 (output) ----
    build_and_aggregate(h2, src2, dst2, cE2, cN3, cHID, hn2, counts, offs, cursor, esrc, bsums);
    out_layer_kernel<<<cN3, 64>>>(h2, hn2, Ws2, Wn2, b2, out);

    (void)in_sizes; (void)n_in; (void)out_size;
}